// round 6
// baseline (speedup 1.0000x reference)
#include <cuda_runtime.h>

// CAM: out[b] = (q[b]@k[b]^T)@v[b] + v1  ==  q[b] @ (k[b]^T @ v[b]) + v1
// B=128, C=1024, N=49 (cols padded to 56). fp32 packed fma.rn.f32x2.
// Packing is over the COLUMN dim (contiguous) -> no smem duplication.
//
// A: grid(128,8)x256 : partial S (128ch) per CTA, 4 groups merged via smem atomics
// R: grid(128)x256   : sum 8 partials -> S_red
// B: grid(128,8)x128 : out-slice(128ch) = q_slice @ S + v_slice

#define BB 128
#define CC 1024
#define NN 49
#define NPAD 56
#define SSZ (NN * NPAD)     // 2744
#define PPA 8
#define PPB 8
#define SC 64               // channels staged per chunk in A

__device__ float SP_glob[BB * PPA * SSZ];   // 11.2 MB partials
__device__ float S_red[BB * SSZ];           // 1.4 MB reduced S

typedef unsigned long long u64;

__device__ __forceinline__ u64 dup2(float x) {
    u64 r; asm("mov.b64 %0, {%1,%1};" : "=l"(r) : "f"(x)); return r;
}
__device__ __forceinline__ void unpack2(u64 p, float& lo, float& hi) {
    asm("mov.b64 {%0,%1}, %2;" : "=f"(lo), "=f"(hi) : "l"(p));
}
__device__ __forceinline__ u64 fma2(u64 a, u64 b, u64 c) {
    u64 d; asm("fma.rn.f32x2 %0, %1, %2, %3;" : "=l"(d) : "l"(a), "l"(b), "l"(c));
    return d;
}

// ---------------- Kernel A: partial S = k_slice^T @ v_slice ----------------
__global__ __launch_bounds__(256)
void cam_partS(const float* __restrict__ k, const float* __restrict__ v) {
    __shared__ __align__(16) float k_sh[SC * NN];    // 12.25 KB natural
    __shared__ __align__(16) float v_sh[SC * NPAD];  // 14.0 KB padded cols
    __shared__ __align__(16) float S_sh[SSZ];        // 10.7 KB  -> 37 KB total

    const int b = blockIdx.x;
    const int p = blockIdx.y;
    const int tid = threadIdx.x;
    const size_t base = ((size_t)b * CC + (size_t)p * 128) * NN;
    const float* kb = k + base;
    const float* vb = v + base;

    // zero S accumulator; zero v pad columns once (never rewritten)
    for (int idx = tid; idx < SSZ; idx += 256) S_sh[idx] = 0.f;
    for (int idx = tid; idx < SC * (NPAD - NN); idx += 256) {
        int cc = idx / (NPAD - NN), ii = NN + idx % (NPAD - NN);
        v_sh[cc * NPAD + ii] = 0.f;
    }

    // 4 groups x 49 threads (tid<196); thread tile = 7 rows x 8 padded cols
    const int g = tid / 49;
    const int t = tid - g * 49;
    const bool active = (g < 4);
    const int ti = (t / 7) * 7;
    const int tj = (t % 7) * 8;

    u64 acc[7][4];
    #pragma unroll
    for (int a = 0; a < 7; a++)
        #pragma unroll
        for (int d = 0; d < 4; d++) acc[a][d] = 0ULL;

    #pragma unroll
    for (int chunk = 0; chunk < 2; chunk++) {
        __syncthreads();
        // stage k natural (float4 copy)
        const float4* k4 = (const float4*)(kb + (size_t)chunk * SC * NN);
        for (int idx = tid; idx < (SC * NN) / 4; idx += 256)
            ((float4*)k_sh)[idx] = k4[idx];
        // stage v into padded rows (coalesced scalar reads)
        const float* vsrc = vb + (size_t)chunk * SC * NN;
        for (int idx = tid; idx < SC * NN; idx += 256) {
            int row = idx / NN, col = idx - row * NN;
            v_sh[row * NPAD + col] = vsrc[idx];
        }
        __syncthreads();

        if (active) {
            #pragma unroll 4
            for (int cl = 0; cl < 16; cl++) {
                const int cc = g * 16 + cl;
                const float* krow = &k_sh[cc * NN + ti];
                const float* vrow = &v_sh[cc * NPAD + tj];
                u64 kp[7], vp[4];
                #pragma unroll
                for (int a = 0; a < 7; a++) kp[a] = dup2(krow[a]);
                #pragma unroll
                for (int d = 0; d < 4; d++) vp[d] = *(const u64*)(vrow + 2 * d);
                #pragma unroll
                for (int a = 0; a < 7; a++)
                    #pragma unroll
                    for (int d = 0; d < 4; d++)
                        acc[a][d] = fma2(kp[a], vp[d], acc[a][d]);
            }
        }
    }

    // merge 4 group-partials in-CTA via smem atomics
    if (active) {
        #pragma unroll
        for (int a = 0; a < 7; a++)
            #pragma unroll
            for (int d = 0; d < 4; d++) {
                float lo, hi;
                unpack2(acc[a][d], lo, hi);
                atomicAdd(&S_sh[(ti + a) * NPAD + tj + 2 * d], lo);
                atomicAdd(&S_sh[(ti + a) * NPAD + tj + 2 * d + 1], hi);
            }
    }
    __syncthreads();

    float4* sp = (float4*)(SP_glob + (size_t)(b * PPA + p) * SSZ);
    for (int idx = tid; idx < SSZ / 4; idx += 256)
        sp[idx] = ((const float4*)S_sh)[idx];
}

// ---------------- Kernel R: reduce 8 partials ----------------
__global__ __launch_bounds__(256)
void cam_reduce() {
    const int b = blockIdx.x;
    const int tid = threadIdx.x;
    const float4* sp = (const float4*)(SP_glob + (size_t)b * PPA * SSZ);
    float4* sr = (float4*)(S_red + (size_t)b * SSZ);
    for (int idx = tid; idx < SSZ / 4; idx += 256) {
        float4 s = sp[idx];
        #pragma unroll
        for (int pp = 1; pp < PPA; pp++) {
            float4 u = sp[pp * (SSZ / 4) + idx];
            s.x += u.x; s.y += u.y; s.z += u.z; s.w += u.w;
        }
        sr[idx] = s;
    }
}

// ---------------- Kernel B: out_slice = q_slice @ S + v_slice ----------------
__global__ __launch_bounds__(128)
void cam_out(const float* __restrict__ q, const float* __restrict__ v,
             float* __restrict__ out) {
    __shared__ __align__(16) float q_sh[128 * NN];   // 25.1 KB natural
    __shared__ __align__(16) float S_sh[SSZ];        // 10.7 KB padded

    const int b = blockIdx.x;
    const int p = blockIdx.y;
    const int tid = threadIdx.x;
    const size_t base = ((size_t)b * CC + (size_t)p * 128) * NN;

    const float4* s4 = (const float4*)(S_red + (size_t)b * SSZ);
    for (int idx = tid; idx < SSZ / 4; idx += 128)
        ((float4*)S_sh)[idx] = s4[idx];
    const float4* q4 = (const float4*)(q + base);
    for (int idx = tid; idx < (128 * NN) / 4; idx += 128)
        ((float4*)q_sh)[idx] = q4[idx];
    __syncthreads();

    // 16 channel-tiles (8 ch) x 7 col-tiles (8 padded cols) = 112 active
    if (tid < 112) {
        const int cg = tid / 7;
        const int jt = (tid - cg * 7) * 8;
        const int cbase = cg * 8;

        u64 acc[8][4];
        #pragma unroll
        for (int a = 0; a < 8; a++)
            #pragma unroll
            for (int d = 0; d < 4; d++) acc[a][d] = 0ULL;

        #pragma unroll 7
        for (int i = 0; i < NN; i++) {
            u64 qp[8], sp_[4];
            #pragma unroll
            for (int a = 0; a < 8; a++) qp[a] = dup2(q_sh[(cbase + a) * NN + i]);
            #pragma unroll
            for (int d = 0; d < 4; d++)
                sp_[d] = *(const u64*)&S_sh[i * NPAD + jt + 2 * d];
            #pragma unroll
            for (int a = 0; a < 8; a++)
                #pragma unroll
                for (int d = 0; d < 4; d++)
                    acc[a][d] = fma2(qp[a], sp_[d], acc[a][d]);
        }

        const float* vb = v + base;
        float* ob = out + base;
        #pragma unroll
        for (int a = 0; a < 8; a++) {
            const int crow = (cbase + a) * NN;
            #pragma unroll
            for (int d = 0; d < 4; d++) {
                float lo, hi;
                unpack2(acc[a][d], lo, hi);
                const int j0 = jt + 2 * d;
                if (j0 < NN)     ob[crow + j0]     = lo + vb[crow + j0];
                if (j0 + 1 < NN) ob[crow + j0 + 1] = hi + vb[crow + j0 + 1];
            }
        }
    }
}

extern "C" void kernel_launch(void* const* d_in, const int* in_sizes, int n_in,
                              void* d_out, int out_size) {
    const float* v1 = (const float*)d_in[0];
    const float* q1 = (const float*)d_in[1];
    const float* k1 = (const float*)d_in[2];
    float* out = (float*)d_out;

    cam_partS<<<dim3(BB, PPA), 256>>>(k1, v1);
    cam_reduce<<<BB, 256>>>();
    cam_out<<<dim3(BB, PPB), 128>>>(q1, v1, out);
}

// round 7
// speedup vs baseline: 1.3671x; 1.3671x over previous
#include <cuda_runtime.h>

// CAM: out[b] = (q[b]@k[b]^T)@v[b] + v1  ==  q[b] @ (k[b]^T @ v[b]) + v1
// B=128, C=1024, N=49 padded to 56 both dims. Packed fma.rn.f32x2.
//
// A: grid(128,16)x128 : partial S (64ch) -> SP_glob.  f32x2 packed over S-ROWS
//    (k rows padded stride 56 -> natural aligned LDS.128 packed loads).
// R: grid(128)x256    : sum 16 partials -> S_red
// B: grid(128,16)x128 : out-slice(64ch) = q_slice @ S + v_slice (cols packed)

#define BB 128
#define CC 1024
#define NN 49
#define NPAD 56
#define SSZ (NPAD * NPAD)   // 3136
#define PPA 16
#define CHA 64
#define PPB 16
#define CHB 64

__device__ float SP_glob[BB * PPA * SSZ];   // 25.7 MB partials
__device__ float S_red[BB * SSZ];           // 1.6 MB reduced S

typedef unsigned long long u64;

__device__ __forceinline__ u64 dup2(float x) {
    u64 r; asm("mov.b64 %0, {%1,%1};" : "=l"(r) : "f"(x)); return r;
}
__device__ __forceinline__ void unpack2(u64 p, float& lo, float& hi) {
    asm("mov.b64 {%0,%1}, %2;" : "=f"(lo), "=f"(hi) : "l"(p));
}
__device__ __forceinline__ u64 fma2(u64 a, u64 b, u64 c) {
    u64 d; asm("fma.rn.f32x2 %0, %1, %2, %3;" : "=l"(d) : "l"(a), "l"(b), "l"(c));
    return d;
}

// ---------------- Kernel A: partial S = k_slice^T @ v_slice ----------------
// thread tile: 8 S-rows (4 f32x2 pairs) x 4 S-cols. 98 active threads cover
// the padded 56x56 S. Each thread owns its tile -> direct global store.
__global__ __launch_bounds__(128)
void cam_partS(const float* __restrict__ k, const float* __restrict__ v) {
    __shared__ __align__(16) float k_sh[CHA * NPAD];  // 14 KB, rows padded+zeroed
    __shared__ __align__(16) float v_sh[CHA * NPAD];  // 14 KB

    const int b = blockIdx.x;
    const int p = blockIdx.y;
    const int tid = threadIdx.x;
    const size_t base = ((size_t)b * CC + (size_t)p * CHA) * NN;
    const float* kb = k + base;
    const float* vb = v + base;

    // stage k,v with row stride 56, zero pad cols 49..55
    for (int idx = tid; idx < CHA * NPAD; idx += 128) {
        const int c = idx / NPAD, i = idx - c * NPAD;
        float kv = 0.f, vv = 0.f;
        if (i < NN) { kv = kb[c * NN + i]; vv = vb[c * NN + i]; }
        k_sh[idx] = kv; v_sh[idx] = vv;
    }
    __syncthreads();

    if (tid < 98) {
        const int rt = tid / 14;            // 0..6
        const int ct = tid - rt * 14;       // 0..13
        const int ti = rt * 8;              // row base 0..48
        const int tj = ct * 4;              // col base 0..52

        u64 acc[4][4];
        #pragma unroll
        for (int a = 0; a < 4; a++)
            #pragma unroll
            for (int d = 0; d < 4; d++) acc[a][d] = 0ULL;

        #pragma unroll 4
        for (int c = 0; c < CHA; c++) {
            const float* krow = &k_sh[c * NPAD + ti];
            const float* vrow = &v_sh[c * NPAD + tj];
            const ulonglong2 k01 = *(const ulonglong2*)(krow);      // rows ti..ti+3
            const ulonglong2 k23 = *(const ulonglong2*)(krow + 4);  // rows ti+4..ti+7
            u64 kp[4] = { k01.x, k01.y, k23.x, k23.y };
            u64 vd[4];
            #pragma unroll
            for (int j = 0; j < 4; j++) vd[j] = dup2(vrow[j]);
            #pragma unroll
            for (int a = 0; a < 4; a++)
                #pragma unroll
                for (int j = 0; j < 4; j++)
                    acc[a][j] = fma2(kp[a], vd[j], acc[a][j]);
        }

        // write tile: for each row-pair, regroup lo/hi into two float4 row stores
        float* sp = SP_glob + (size_t)(b * PPA + p) * SSZ;
        #pragma unroll
        for (int a = 0; a < 4; a++) {
            float lo0, hi0, lo1, hi1, lo2, hi2, lo3, hi3;
            unpack2(acc[a][0], lo0, hi0);
            unpack2(acc[a][1], lo1, hi1);
            unpack2(acc[a][2], lo2, hi2);
            unpack2(acc[a][3], lo3, hi3);
            *(float4*)&sp[(ti + 2 * a) * NPAD + tj]     = make_float4(lo0, lo1, lo2, lo3);
            *(float4*)&sp[(ti + 2 * a + 1) * NPAD + tj] = make_float4(hi0, hi1, hi2, hi3);
        }
    }
}

// ---------------- Kernel R: reduce 16 partials ----------------
__global__ __launch_bounds__(256)
void cam_reduce() {
    const int b = blockIdx.x;
    const int tid = threadIdx.x;
    const float4* sp = (const float4*)(SP_glob + (size_t)b * PPA * SSZ);
    float4* sr = (float4*)(S_red + (size_t)b * SSZ);
    for (int idx = tid; idx < SSZ / 4; idx += 256) {
        float4 s = sp[idx];
        #pragma unroll
        for (int pp = 1; pp < PPA; pp++) {
            float4 u = sp[pp * (SSZ / 4) + idx];
            s.x += u.x; s.y += u.y; s.z += u.z; s.w += u.w;
        }
        sr[idx] = s;
    }
}

// ---------------- Kernel B: out_slice = q_slice @ S + v_slice ----------------
// thread tile: 4 channels x 8 cols (4 f32x2 col-pairs). 112 active threads.
__global__ __launch_bounds__(128)
void cam_out(const float* __restrict__ q, const float* __restrict__ v,
             float* __restrict__ out) {
    __shared__ __align__(16) float2 q_dup[CHB * NN];  // 25.1 KB (q,q) pairs
    __shared__ __align__(16) float  S_sh[SSZ];        // 12.25 KB

    const int b = blockIdx.x;
    const int p = blockIdx.y;
    const int tid = threadIdx.x;
    const size_t base = ((size_t)b * CC + (size_t)p * CHB) * NN;

    const float4* s4 = (const float4*)(S_red + (size_t)b * SSZ);
    for (int idx = tid; idx < SSZ / 4; idx += 128)
        ((float4*)S_sh)[idx] = s4[idx];
    const float* qs = q + base;
    for (int idx = tid; idx < CHB * NN; idx += 128) {
        const float x = qs[idx];
        q_dup[idx] = make_float2(x, x);
    }
    __syncthreads();

    if (tid < 112) {
        const int cg = tid / 7;             // 0..15
        const int jt = (tid - cg * 7) * 8;  // 0..48
        const int cbase = cg * 4;

        u64 acc[4][4];
        #pragma unroll
        for (int a = 0; a < 4; a++)
            #pragma unroll
            for (int d = 0; d < 4; d++) acc[a][d] = 0ULL;

        #pragma unroll 7
        for (int i = 0; i < NN; i++) {
            u64 qp[4];
            #pragma unroll
            for (int a = 0; a < 4; a++)
                qp[a] = *(const u64*)&q_dup[(cbase + a) * NN + i];
            const ulonglong2 s01 = *(const ulonglong2*)&S_sh[i * NPAD + jt];
            const ulonglong2 s23 = *(const ulonglong2*)&S_sh[i * NPAD + jt + 4];
            u64 sp_[4] = { s01.x, s01.y, s23.x, s23.y };
            #pragma unroll
            for (int a = 0; a < 4; a++)
                #pragma unroll
                for (int d = 0; d < 4; d++)
                    acc[a][d] = fma2(qp[a], sp_[d], acc[a][d]);
        }

        const float* vb = v + base;
        float* ob = out + base;
        #pragma unroll
        for (int a = 0; a < 4; a++) {
            const int crow = (cbase + a) * NN;
            #pragma unroll
            for (int d = 0; d < 4; d++) {
                float lo, hi;
                unpack2(acc[a][d], lo, hi);
                const int j0 = jt + 2 * d;
                if (j0 < NN)     ob[crow + j0]     = lo + vb[crow + j0];
                if (j0 + 1 < NN) ob[crow + j0 + 1] = hi + vb[crow + j0 + 1];
            }
        }
    }
}

extern "C" void kernel_launch(void* const* d_in, const int* in_sizes, int n_in,
                              void* d_out, int out_size) {
    const float* v1 = (const float*)d_in[0];
    const float* q1 = (const float*)d_in[1];
    const float* k1 = (const float*)d_in[2];
    float* out = (float*)d_out;

    cam_partS<<<dim3(BB, PPA), 128>>>(k1, v1);
    cam_reduce<<<BB, 256>>>();
    cam_out<<<dim3(BB, PPB), 128>>>(q1, v1, out);
}